// round 16
// baseline (speedup 1.0000x reference)
#include <cuda_runtime.h>
#include <cuda_bf16.h>
#include <cstdint>

typedef unsigned long long ull;
typedef __nv_bfloat16 bf16;

#define TOKENS 4096
#define PDIM   1024
#define PHALF  512
#define NKEYS  512
#define PTOPK  32

// ---------------- scratch (static device arrays; no cudaMalloc) ----------------
__device__ float g_gate [TOKENS * PDIM];
__device__ float g_s1   [TOKENS * NKEYS];
__device__ float g_s2   [TOKENS * NKEYS];
__device__ int   g_tidx [TOKENS * PTOPK];
__device__ float g_tw   [TOKENS * PTOPK];
__device__ float g_c1   [NKEYS];
__device__ float g_c2   [NKEYS];

// bf16-split operand buffers (K concatenated by slot count)
__device__ bf16 g_x6  [(size_t)TOKENS * PDIM * 6];   // x, 6-slot A-mode
__device__ bf16 g_x3  [(size_t)TOKENS * PDIM * 3];   // x, 3-slot A-mode
__device__ bf16 g_m3  [(size_t)TOKENS * PDIM * 3];   // gathered*gate, 3-slot A-mode
__device__ bf16 g_wg3 [(size_t)PDIM * PDIM * 3];
__device__ bf16 g_wo3 [(size_t)PDIM * PDIM * 3];
__device__ bf16 g_k16a[(size_t)NKEYS * PHALF * 6];   // ke1, 6-slot A-mode
__device__ bf16 g_k26a[(size_t)NKEYS * PHALF * 6];   // ke2, 6-slot A-mode
__device__ bf16 g_wqt6a[(size_t)PDIM * PHALF * 6];   // Wq[0:512,:]^T, 6-slot B-mode
__device__ bf16 g_wqt6b[(size_t)PDIM * PHALF * 6];   // Wq[512:,:]^T,  6-slot B-mode
__device__ bf16 g_m16 [(size_t)NKEYS * PDIM * 6];    // M1 = ke1@Wq1, 6-slot B-mode
__device__ bf16 g_m26 [(size_t)NKEYS * PDIM * 6];    // M2 = ke2@Wq2, 6-slot B-mode

// ---------------- helpers ----------------
__device__ __forceinline__ uint32_t smem_u32(const void* p) {
    uint32_t a;
    asm("{ .reg .u64 t; cvta.to.shared.u64 t, %1; cvt.u32.u64 %0, t; }" : "=r"(a) : "l"(p));
    return a;
}
#define LDSM4(r0, r1, r2, r3, addr)                                             \
    asm volatile("ldmatrix.sync.aligned.m8n8.x4.shared.b16 {%0,%1,%2,%3}, [%4];" \
                 : "=r"(r0), "=r"(r1), "=r"(r2), "=r"(r3) : "r"(addr))
#define MMA16816(c, a0, a1, a2, a3, b0, b1)                                     \
    asm volatile("mma.sync.aligned.m16n8k16.row.col.f32.bf16.bf16.f32 "         \
                 "{%0,%1,%2,%3}, {%4,%5,%6,%7}, {%8,%9}, {%0,%1,%2,%3};"        \
                 : "+f"((c)[0]), "+f"((c)[1]), "+f"((c)[2]), "+f"((c)[3])        \
                 : "r"(a0), "r"(a1), "r"(a2), "r"(a3), "r"(b0), "r"(b1))
__device__ __forceinline__ void cpa16(uint32_t s, const bf16* g) {
    asm volatile("cp.async.cg.shared.global [%0], [%1], 16;" :: "r"(s), "l"(g) : "memory");
}
__device__ __forceinline__ void cpa_commit() {
    asm volatile("cp.async.commit_group;" ::: "memory");
}
__device__ __forceinline__ void cpa_wait1() {
    asm volatile("cp.async.wait_group 1;" ::: "memory");
}
// SW64-style swizzle: 16B-granule index (bits 4:5) ^= row bits 1:2 (bits 7:8).
__device__ __forceinline__ uint32_t swz(uint32_t off) { return off ^ ((off >> 3) & 0x30); }
__device__ __forceinline__ uint32_t pk2(bf16 a, bf16 b) {
    uint16_t lo = *(uint16_t*)&a, hi = *(uint16_t*)&b;
    return (uint32_t)lo | ((uint32_t)hi << 16);
}
__device__ __forceinline__ void split3(float a, bf16* p) {
    p[0] = __float2bfloat16(a);
    float r1 = a - __bfloat162float(p[0]);
    p[1] = __float2bfloat16(r1);
    p[2] = __float2bfloat16(r1 - __bfloat162float(p[1]));
}

// ---------------- split kernels ----------------
// Exact 3-part residual split a = h+m+l. Slot orders:
//  6-slot: A{h,h,m,h,l,m} x B{h,m,h,l,h,m} -> hh,hm,mh,hl,lh,mm (err ~2^-27)
//  3-slot: A{h,h,m}       x B{h,m,h}       -> hh,hm,mh          (err ~2^-18)
template <int NS, int MODE>
__global__ void splitN(const float* __restrict__ X, bf16* __restrict__ Y,
                       int total4, int Kin, int ldx)
{
    int idx = blockIdx.x * blockDim.x + threadIdx.x;
    if (idx >= total4) return;
    const int Kin4 = Kin >> 2;
    int r = idx / Kin4, k4 = (idx - r * Kin4) << 2;
    float4 a4 = *(const float4*)&X[(size_t)r * ldx + k4];
    float av[4] = { a4.x, a4.y, a4.z, a4.w };
    bf16 P[3][4];
    #pragma unroll
    for (int j = 0; j < 4; j++) {
        bf16 t[3]; split3(av[j], t);
        P[0][j] = t[0]; P[1][j] = t[1]; P[2][j] = t[2];
    }
    const int PA6[6] = {0,0,1,0,2,1};
    const int PB6[6] = {0,1,0,2,0,1};
    const int PA3[3] = {0,0,1};
    const int PB3[3] = {0,1,0};
    size_t base = (size_t)r * (NS * Kin) + k4;
    #pragma unroll
    for (int p = 0; p < NS; p++) {
        int sel = (NS == 6) ? (MODE ? PB6[p] : PA6[p]) : (MODE ? PB3[p] : PA3[p]);
        *(uint2*)&Y[base + (size_t)p * Kin] = *(uint2*)P[sel];
    }
}

// fused x -> x6 (6-slot A) + x3 (3-slot A); reads x once
__global__ void splitX(const float* __restrict__ X, bf16* __restrict__ Y6,
                       bf16* __restrict__ Y3, int total4)
{
    int idx = blockIdx.x * blockDim.x + threadIdx.x;
    if (idx >= total4) return;
    int r = idx / (PDIM / 4), k4 = (idx - r * (PDIM / 4)) << 2;
    float4 a4 = *(const float4*)&X[(size_t)r * PDIM + k4];
    float av[4] = { a4.x, a4.y, a4.z, a4.w };
    bf16 P[3][4];
    #pragma unroll
    for (int j = 0; j < 4; j++) {
        bf16 t[3]; split3(av[j], t);
        P[0][j] = t[0]; P[1][j] = t[1]; P[2][j] = t[2];
    }
    const int PA6[6] = {0,0,1,0,2,1};
    size_t b6 = (size_t)r * (6 * PDIM) + k4;
    #pragma unroll
    for (int p = 0; p < 6; p++)
        *(uint2*)&Y6[b6 + (size_t)p * PDIM] = *(uint2*)P[PA6[p]];
    const int PA3[3] = {0,0,1};
    size_t b3 = (size_t)r * (3 * PDIM) + k4;
    #pragma unroll
    for (int p = 0; p < 3; p++)
        *(uint2*)&Y3[b3 + (size_t)p * PDIM] = *(uint2*)P[PA3[p]];
}

// transpose-split: Wq (1024x1024, rows e) -> WqT 6-slot B-mode, halves by e.
// outA[d, slot*512 + h] = part(Wq[h, d]),   h in [0,512)
// outB[d, slot*512 + h-512],                h in [512,1024)
__global__ void tsplit_wq(const float* __restrict__ Wq,
                          bf16* __restrict__ outA, bf16* __restrict__ outB)
{
    __shared__ float t[32][33];
    const int d0 = blockIdx.x * 32;
    const int h0 = blockIdx.y * 32;
    const int tx = threadIdx.x & 31, ty = threadIdx.x >> 5;  // 256 thr
    #pragma unroll
    for (int j = 0; j < 32; j += 8)
        t[ty + j][tx] = Wq[(size_t)(h0 + ty + j) * PDIM + d0 + tx];
    __syncthreads();
    bf16* out = (h0 < PHALF) ? outA : outB;
    const int hl = (h0 & (PHALF - 1)) + tx;
    const int PB6[6] = {0,1,0,2,0,1};
    #pragma unroll
    for (int j = 0; j < 32; j += 8) {
        const int d = d0 + ty + j;
        bf16 p[3]; split3(t[tx][ty + j], p);
        size_t base = (size_t)d * (6 * PHALF) + hl;
        #pragma unroll
        for (int s = 0; s < 6; s++)
            out[base + (size_t)s * PHALF] = p[PB6[s]];
    }
}

// folded bias: c1[k] = ke1[k,:]·bq[0:512], c2[k] = ke2[k,:]·bq[512:1024]
__global__ void cbias_kernel(const float* __restrict__ ke1, const float* __restrict__ ke2,
                             const float* __restrict__ bq,
                             float* __restrict__ c1, float* __restrict__ c2)
{
    int k = blockIdx.x * blockDim.x + threadIdx.x;
    if (k >= NKEYS) return;
    float s1 = 0.f, s2 = 0.f;
    for (int h = 0; h < PHALF; h++) {
        s1 += ke1[k * PHALF + h] * bq[h];
        s2 += ke2[k * PHALF + h] * bq[PHALF + h];
    }
    c1[k] = s1; c2[k] = s2;
}

// ---------------- HMMA bf16 TN GEMM with cp.async 3-stage pipeline ----------------
// C[M,N] = A[M,K]*B[N,K]^T (+bias, silu). BM=BN=128, BK=32, 8 warps (4m x 2n).
// smem: 64B rows + XOR swizzle, 3 stages of 16KB = 48KB (no opt-in).
// esplit=1: epilogue writes 6-slot B-mode split of raw acc into bf16 C
// (row*(6*sstr) + slot*sstr + col) — used to emit M1/M2 pre-split.
#define STG    16384
#define NSTG   3
#define SMEMSZ 49152

__global__ __launch_bounds__(256, 2)
void gemm_mma(const bf16* __restrict__ A0, const bf16* __restrict__ A1,
              const bf16* __restrict__ B0, const bf16* __restrict__ B1,
              const float* __restrict__ bias0, const float* __restrict__ bias1,
              float* __restrict__ C0, float* __restrict__ C1,
              int ldc0, int ldc1, int K0, int K1, int nx0, int act0, int act1,
              int esplit, int sstr)
{
    extern __shared__ char smem[];
    const uint32_t sb = smem_u32(smem);

    const bool sec = (int)blockIdx.x >= nx0;
    const bf16* A     = sec ? A1 : A0;
    const bf16* B     = sec ? B1 : B0;
    const float* bias = sec ? bias1 : bias0;
    float* C          = sec ? C1 : C0;
    const int ldc     = sec ? ldc1 : ldc0;
    const int K       = sec ? K1 : K0;
    const int act     = sec ? act1 : act0;
    const int bn      = (sec ? (int)blockIdx.x - nx0 : (int)blockIdx.x) * 128;
    const int bm      = blockIdx.y * 128;

    const int tid = threadIdx.x, wid = tid >> 5, lane = tid & 31;
    const int wm = wid & 3, wn = wid >> 2;

    const int lr = tid >> 2, lq = tid & 3;
    const bf16* Ag = A + (size_t)(bm + lr) * K + lq * 8;
    const bf16* Bg = B + (size_t)(bn + lr) * K + lq * 8;
    const uint32_t wloc = swz(lr * 64 + lq * 16);
    const uint32_t wA = sb + wloc;
    const uint32_t wB = wA + 8192;

    const int arow = wm * 32 + (lane & 15);
    uint32_t aAd[2][2];
    #pragma unroll
    for (int mt = 0; mt < 2; mt++)
        #pragma unroll
        for (int ks = 0; ks < 2; ks++)
            aAd[mt][ks] = sb + swz((arow + mt * 16) * 64 + ks * 32 + (lane >> 4) * 16);
    const int brow = wn * 64 + (lane & 7) + ((lane >> 4) & 1) * 8;
    uint32_t bAd[2];
    #pragma unroll
    for (int ks = 0; ks < 2; ks++)
        bAd[ks] = sb + 8192 + swz(brow * 64 + ks * 32 + ((lane >> 3) & 1) * 16);

    float acc[2][8][4];
    #pragma unroll
    for (int mt = 0; mt < 2; mt++)
        #pragma unroll
        for (int nt = 0; nt < 8; nt++)
            #pragma unroll
            for (int c = 0; c < 4; c++) acc[mt][nt][c] = 0.f;

    const int NT = K >> 5;

    #pragma unroll
    for (int s = 0; s < NSTG - 1; s++) {
        const int k0 = s * 32;
        const uint32_t off = s * STG;
        cpa16(wA + off, Ag + k0);
        cpa16(wA + off + 4096, Ag + (size_t)64 * K + k0);
        cpa16(wB + off, Bg + k0);
        cpa16(wB + off + 4096, Bg + (size_t)64 * K + k0);
        cpa_commit();
    }

    int st = 0;
    for (int i = 0; i < NT; i++) {
        cpa_wait1();
        __syncthreads();
        const int kn = i + NSTG - 1;
        if (kn < NT) {
            const int k0 = kn * 32;
            const int sn = st + NSTG - 1 - ((st + NSTG - 1 >= NSTG) ? NSTG : 0);
            const uint32_t off = sn * STG;
            cpa16(wA + off, Ag + k0);
            cpa16(wA + off + 4096, Ag + (size_t)64 * K + k0);
            cpa16(wB + off, Bg + k0);
            cpa16(wB + off + 4096, Bg + (size_t)64 * K + k0);
        }
        cpa_commit();

        const uint32_t so = st * STG;
        #pragma unroll
        for (int ks = 0; ks < 2; ks++) {
            uint32_t a0, a1, a2, a3, a4, a5, a6, a7;
            LDSM4(a0, a1, a2, a3, aAd[0][ks] + so);
            LDSM4(a4, a5, a6, a7, aAd[1][ks] + so);
            #pragma unroll
            for (int p = 0; p < 4; p++) {
                uint32_t b0, b1, b2, b3;
                LDSM4(b0, b1, b2, b3, bAd[ks] + so + p * 1024);
                MMA16816(acc[0][2*p],   a0, a1, a2, a3, b0, b1);
                MMA16816(acc[1][2*p],   a4, a5, a6, a7, b0, b1);
                MMA16816(acc[0][2*p+1], a0, a1, a2, a3, b2, b3);
                MMA16816(acc[1][2*p+1], a4, a5, a6, a7, b2, b3);
            }
        }
        st = (st + 1 == NSTG) ? 0 : st + 1;
    }

    // epilogue
    const int colb = bn + wn * 64 + (lane & 3) * 2;
    if (!esplit) {
        #pragma unroll
        for (int mt = 0; mt < 2; mt++) {
            const int r0 = bm + wm * 32 + mt * 16 + (lane >> 2);
            #pragma unroll
            for (int h = 0; h < 2; h++) {
                const int row = r0 + h * 8;
                #pragma unroll
                for (int nt = 0; nt < 8; nt++) {
                    const int col = colb + nt * 8;
                    float v0 = acc[mt][nt][h * 2 + 0];
                    float v1 = acc[mt][nt][h * 2 + 1];
                    if (bias) { v0 += bias[col]; v1 += bias[col + 1]; }
                    if (act) {
                        v0 *= 1.f / (1.f + __expf(-v0));
                        v1 *= 1.f / (1.f + __expf(-v1));
                    }
                    *(float2*)&C[(size_t)row * ldc + col] = make_float2(v0, v1);
                }
            }
        }
    } else {
        // write 6-slot B-mode split of raw accumulators (no bias/act)
        bf16* Cb = (bf16*)C;
        const int PB6[6] = {0,1,0,2,0,1};
        #pragma unroll
        for (int mt = 0; mt < 2; mt++) {
            const int r0 = bm + wm * 32 + mt * 16 + (lane >> 2);
            #pragma unroll
            for (int h = 0; h < 2; h++) {
                const int row = r0 + h * 8;
                size_t rb = (size_t)row * (6 * sstr);
                #pragma unroll
                for (int nt = 0; nt < 8; nt++) {
                    const int col = colb + nt * 8;
                    bf16 p0[3], p1[3];
                    split3(acc[mt][nt][h * 2 + 0], p0);
                    split3(acc[mt][nt][h * 2 + 1], p1);
                    #pragma unroll
                    for (int s = 0; s < 6; s++)
                        *(uint32_t*)&Cb[rb + (size_t)s * sstr + col] =
                            pk2(p0[PB6[s]], p1[PB6[s]]);
                }
            }
        }
    }
}

// ---------------- top-k (warp per token, registers only) ----------------
__device__ __forceinline__ unsigned ford(float v) {
    unsigned u = __float_as_uint(v);
    return (u & 0x80000000u) ? ~u : (u | 0x80000000u);
}
__device__ __forceinline__ float funord(unsigned k) {
    unsigned u = (k & 0x80000000u) ? (k ^ 0x80000000u) : ~k;
    return __uint_as_float(u);
}
__device__ __forceinline__ ull mkkey(float v, int idx) {
    return ((ull)ford(v) << 32) | (unsigned)(0xFFFFFFFFu - (unsigned)idx);
}

__device__ __forceinline__ void select32_512(ull* kk, int lane, float &ov, int &oi) {
    for (int it = 0; it < PTOPK; ++it) {
        ull best = kk[0];
        #pragma unroll
        for (int j = 1; j < 16; j++) if (kk[j] > best) best = kk[j];
        #pragma unroll
        for (int o = 16; o > 0; o >>= 1) {
            ull t = __shfl_xor_sync(0xFFFFFFFFu, best, o);
            if (t > best) best = t;
        }
        int idx = (int)(0xFFFFFFFFu - (unsigned)best);
        if (lane == it) { ov = funord((unsigned)(best >> 32)); oi = idx; }
        int owner = idx & 31;
        int slot  = idx >> 5;
        if (lane == owner) {
            #pragma unroll
            for (int j = 0; j < 16; j++) if (j == slot) kk[j] = 0ull;
        }
    }
}

__global__ void topk_kernel() {
    const int gw   = (blockIdx.x * blockDim.x + threadIdx.x) >> 5;
    const int lane = threadIdx.x & 31;
    const float* s1 = g_s1 + (size_t)gw * NKEYS;
    const float* s2 = g_s2 + (size_t)gw * NKEYS;

    float s1v = 0.f, s2v = 0.f, selv = 0.f;
    int   s1i = 0,   s2i = 0,   selp = 0;

    {
        ull kk[16];
        #pragma unroll
        for (int j = 0; j < 16; j++) { int idx = j * 32 + lane; kk[j] = mkkey(s1[idx], idx); }
        select32_512(kk, lane, s1v, s1i);
    }
    {
        ull kk[16];
        #pragma unroll
        for (int j = 0; j < 16; j++) { int idx = j * 32 + lane; kk[j] = mkkey(s2[idx], idx); }
        select32_512(kk, lane, s2v, s2i);
    }

    // Stage 3: sorted-merge pointer walk over the 32x32 sum grid.
    {
        int p = 0;
        float v = s1v + __shfl_sync(0xFFFFFFFFu, s2v, 0);
        for (int it = 0; it < PTOPK; ++it) {
            float bv = v;
            #pragma unroll
            for (int o = 16; o > 0; o >>= 1)
                bv = fmaxf(bv, __shfl_xor_sync(0xFFFFFFFFu, bv, o));
            unsigned m = __ballot_sync(0xFFFFFFFFu, v == bv);
            int wl = __ffs(m) - 1;
            int wp = __shfl_sync(0xFFFFFFFFu, p, wl);
            if (lane == it) { selv = bv; selp = wl * 32 + wp; }
            bool won = (lane == wl);
            p += won;
            float ns2 = __shfl_sync(0xFFFFFFFFu, s2v, p < 32 ? p : 31);
            if (won) v = (p < 32) ? (s1v + ns2) : -3.4e38f;
        }
    }

    float mx = __shfl_sync(0xFFFFFFFFu, selv, 0);
    float e = __expf((selv - mx) * 0.03125f);
    float s = e;
    #pragma unroll
    for (int o = 16; o > 0; o >>= 1) s += __shfl_xor_sync(0xFFFFFFFFu, s, o);
    float w = e / s;

    int i1 = __shfl_sync(0xFFFFFFFFu, s1i, selp >> 5);
    int i2 = __shfl_sync(0xFFFFFFFFu, s2i, selp & 31);
    g_tidx[gw * PTOPK + lane] = i1 * NKEYS + i2;
    g_tw  [gw * PTOPK + lane] = w;
}

// ---------------- gather + weighted sum + gate -> 3-slot split (fused) ----------
__global__ void gather_kernel(const float* __restrict__ values) {
    const int token = blockIdx.x;
    const int tid   = threadIdx.x;
    __shared__ int   sidx[PTOPK];
    __shared__ float sw  [PTOPK];
    if (tid < PTOPK) {
        sidx[tid] = g_tidx[token * PTOPK + tid];
        sw  [tid] = g_tw  [token * PTOPK + tid];
    }
    __syncthreads();

    float4 acc = make_float4(0.f, 0.f, 0.f, 0.f);
    #pragma unroll 8
    for (int k = 0; k < PTOPK; k++) {
        const float4* rowp = (const float4*)(values + (size_t)sidx[k] * PDIM);
        float4 v = __ldg(rowp + tid);
        float wk = sw[k];
        acc.x += wk * v.x; acc.y += wk * v.y; acc.z += wk * v.z; acc.w += wk * v.w;
    }
    float4 g = ((const float4*)(g_gate + (size_t)token * PDIM))[tid];
    acc.x *= g.x; acc.y *= g.y; acc.z *= g.z; acc.w *= g.w;

    // write 3-slot A-mode split {h,h,m} directly (feeds G3); no fp32 mid buffer
    float av[4] = { acc.x, acc.y, acc.z, acc.w };
    bf16 hh[4], mm[4];
    #pragma unroll
    for (int j = 0; j < 4; j++) {
        hh[j] = __float2bfloat16(av[j]);
        mm[j] = __float2bfloat16(av[j] - __bfloat162float(hh[j]));
    }
    uint2 hu = make_uint2(pk2(hh[0], hh[1]), pk2(hh[2], hh[3]));
    uint2 mu = make_uint2(pk2(mm[0], mm[1]), pk2(mm[2], mm[3]));
    size_t rb = (size_t)token * (3 * PDIM) + tid * 4;
    *(uint2*)&g_m3[rb]            = hu;   // slot 0: h
    *(uint2*)&g_m3[rb + PDIM]     = hu;   // slot 1: h
    *(uint2*)&g_m3[rb + 2 * PDIM] = mu;   // slot 2: m
}

// ---------------- launch ----------------
extern "C" void kernel_launch(void* const* d_in, const int* in_sizes, int n_in,
                              void* d_out, int out_size) {
    (void)in_sizes; (void)n_in; (void)out_size;
    const float* x      = (const float*)d_in[0];
    const float* ke1    = (const float*)d_in[1];
    const float* ke2    = (const float*)d_in[2];
    const float* values = (const float*)d_in[3];
    const float* Wq     = (const float*)d_in[4];
    const float* bq     = (const float*)d_in[5];
    const float* Wg     = (const float*)d_in[6];
    const float* bg     = (const float*)d_in[7];
    const float* Wo     = (const float*)d_in[8];
    const float* bo     = (const float*)d_in[9];
    float* out = (float*)d_out;

    float *gt, *s1, *s2, *c1, *c2;
    bf16 *x6, *x3, *m3, *wg3, *wo3, *k16a, *k26a, *wqt6a, *wqt6b, *m16, *m26;
    cudaGetSymbolAddress((void**)&gt,    g_gate);
    cudaGetSymbolAddress((void**)&s1,    g_s1);
    cudaGetSymbolAddress((void**)&s2,    g_s2);
    cudaGetSymbolAddress((void**)&c1,    g_c1);
    cudaGetSymbolAddress((void**)&c2,    g_c2);
    cudaGetSymbolAddress((void**)&x6,    g_x6);
    cudaGetSymbolAddress((void**)&x3,    g_x3);
    cudaGetSymbolAddress((void**)&m3,    g_m3);
    cudaGetSymbolAddress((void**)&wg3,   g_wg3);
    cudaGetSymbolAddress((void**)&wo3,   g_wo3);
    cudaGetSymbolAddress((void**)&k16a,  g_k16a);
    cudaGetSymbolAddress((void**)&k26a,  g_k26a);
    cudaGetSymbolAddress((void**)&wqt6a, g_wqt6a);
    cudaGetSymbolAddress((void**)&wqt6b, g_wqt6b);
    cudaGetSymbolAddress((void**)&m16,   g_m16);
    cudaGetSymbolAddress((void**)&m26,   g_m26);

    const int T = 256;
    // operand prep
    tsplit_wq<<<dim3(32, 32), T>>>(Wq, wqt6a, wqt6b);
    splitN<6,0><<<(NKEYS * PHALF / 4 + T - 1) / T, T>>>(ke1, k16a, NKEYS * PHALF / 4, PHALF, PHALF);
    splitN<6,0><<<(NKEYS * PHALF / 4 + T - 1) / T, T>>>(ke2, k26a, NKEYS * PHALF / 4, PHALF, PHALF);
    cbias_kernel<<<2, T>>>(ke1, ke2, bq, c1, c2);
    splitX<<<(TOKENS * PDIM / 4 + T - 1) / T, T>>>(x, x6, x3, TOKENS * PDIM / 4);
    splitN<3,1><<<(PDIM * PDIM / 4 + T - 1) / T, T>>>(Wg, wg3, PDIM * PDIM / 4, PDIM, PDIM);
    splitN<3,1><<<(PDIM * PDIM / 4 + T - 1) / T, T>>>(Wo, wo3, PDIM * PDIM / 4, PDIM, PDIM);

    // M-build: M1 = ke1@Wq[0:512,:]  ||  M2 = ke2@Wq[512:,:]   (emit pre-split, 6-slot B)
    gemm_mma<<<dim3(16, NKEYS / 128), T, SMEMSZ>>>(
        k16a, k26a, wqt6a, wqt6b, nullptr, nullptr,
        (float*)m16, (float*)m26, 0, 0,
        PHALF * 6, PHALF * 6, /*nx0=*/8, 0, 0, /*esplit=*/1, /*sstr=*/PDIM);

    // gate = silu(x@Wg^T + bg)   (3-slot)
    gemm_mma<<<dim3(8, TOKENS / 128), T, SMEMSZ>>>(
        x3, x3, wg3, wg3, bg, bg, gt, gt, PDIM, PDIM,
        PDIM * 3, PDIM * 3, /*nx0=*/8, 1, 1, 0, 0);

    // scores: s1 = x@M1^T + c1 || s2 = x@M2^T + c2   (6-slot, K6=6144)
    gemm_mma<<<dim3(8, TOKENS / 128), T, SMEMSZ>>>(
        x6, x6, m16, m26, c1, c2, s1, s2, NKEYS, NKEYS,
        PDIM * 6, PDIM * 6, /*nx0=*/4, 0, 0, 0, 0);

    topk_kernel<<<TOKENS / 8, 256>>>();
    gather_kernel<<<TOKENS, 256>>>(values);   // writes m3 (3-slot) directly

    // out = (gathered*gate)@Wo^T + bo   (3-slot)
    gemm_mma<<<dim3(8, TOKENS / 128), T, SMEMSZ>>>(
        m3, m3, wo3, wo3, bo, bo, out, out, PDIM, PDIM,
        PDIM * 3, PDIM * 3, /*nx0=*/8, 0, 0, 0, 0);
}